// round 4
// baseline (speedup 1.0000x reference)
#include <cuda_runtime.h>
#include <cuda_bf16.h>

// Problem constants
#define H   1024
#define B   64
#define S   512
#define W3H 3072            // W row stride (3*H)
#define NPROD 128           // u2 producer blocks
#define NBLK  4096          // total blocks (8 rows each)

// Scratch (zero-initialized at module load; every launch self-cleans, so each
// graph replay is deterministic).
__device__ float g_u2[H];            // u2 = W[:, 2H:3H]^T v   (accumulated, reset at end)
__device__ float g_scores[B * S];    // pre-softmax scores
__device__ int   g_cnt[B];           // per-b completion counters (reset by per-b last)
__device__ int   g_gcnt;             // global softmax counter (reset by global last)
__device__ int   g_ready;            // u2 producer completion counter (reset by global last)

// ---------------------------------------------------------------------------
// Megakernel: u2 (blocks 0..127) -> flag -> streaming scores -> per-b softmax
// grid = 4096 blocks x 256 threads. Block bid handles rows [bid*8, bid*8+8),
// b = bid>>6. Producers are guaranteed wave-1 resident, so the spin is safe.
// ---------------------------------------------------------------------------
__global__ void k_mega(const float*  __restrict__ W,
                       const float*  __restrict__ v,
                       const float4* __restrict__ enc,
                       float*        __restrict__ out) {
    const int bid = blockIdx.x;
    const int tid = threadIdx.x;

    __shared__ float4 s_red[4][64];   // producer partial reduce
    __shared__ float4 s_u2[H / 4];    // staged u2 (4 KB)
    __shared__ float  s_sm[256];      // softmax reduce
    __shared__ int    s_ticket;

    // ---------------- Phase 1: u2 producers ----------------
    if (bid < NPROD) {
        const int tx = tid & 63;            // k-float4 lane
        const int ty = tid >> 6;            // h slice (0..3)
        const int k4 = (bid & 3) * 64 + tx;
        const int h0 = (bid >> 2) * 32 + ty;

        float4 acc = make_float4(0.f, 0.f, 0.f, 0.f);
#pragma unroll
        for (int j = 0; j < 8; j++) {
            const int h = h0 + j * 4;
            const float vh = __ldg(&v[h]);
            const float4 w = __ldg((const float4*)(W + (size_t)h * W3H + 2 * H) + k4);
            acc.x += vh * w.x;
            acc.y += vh * w.y;
            acc.z += vh * w.z;
            acc.w += vh * w.w;
        }
        s_red[ty][tx] = acc;
        __syncthreads();
        if (ty == 0) {
            float4 s = s_red[0][tx];
#pragma unroll
            for (int j = 1; j < 4; j++) {
                const float4 p = s_red[j][tx];
                s.x += p.x; s.y += p.y; s.z += p.z; s.w += p.w;
            }
            float* dst = g_u2 + k4 * 4;
            atomicAdd(dst + 0, s.x);
            atomicAdd(dst + 1, s.y);
            atomicAdd(dst + 2, s.z);
            atomicAdd(dst + 3, s.w);
        }
        __threadfence();                 // release: u2 adds visible before flag
        __syncthreads();
        if (tid == 0) atomicAdd(&g_ready, 1);
    }

    // ---------------- Phase 2: wait for u2, stage into shared ----------------
    if (tid == 0) {
        while (*(volatile int*)&g_ready < NPROD) __nanosleep(32);
        __threadfence();                 // acquire
    }
    __syncthreads();
    s_u2[tid] = __ldcg(((const float4*)g_u2) + tid);   // L2-coherent, fresh
    __syncthreads();

    // ---------------- Phase 3: streaming scores ----------------
    const int b    = bid >> 6;
    const int warp = tid >> 5;
    const int lane = tid & 31;
    const int row  = bid * 8 + warp;     // global row in [0, B*S)

    const float4* __restrict__ rp = enc + (size_t)row * (H / 4);

    float acc = 0.f;
#pragma unroll
    for (int j = 0; j < 8; j++) {
        const float4 e = __ldg(&rp[lane + j * 32]);
        const float4 w = s_u2[lane + j * 32];
        acc += e.x * w.x + e.y * w.y + e.z * w.z + e.w * w.w;
    }
#pragma unroll
    for (int off = 16; off > 0; off >>= 1)
        acc += __shfl_xor_sync(0xffffffffu, acc, off);
    if (lane == 0) g_scores[row] = acc;

    // ---------------- Phase 4: per-b ticket -> softmax + self-clean ----------
    __threadfence();
    __syncthreads();
    if (tid == 0) s_ticket = atomicAdd(&g_cnt[b], 1);
    __syncthreads();

    if (s_ticket == 63) {
        const float* sc = g_scores + b * S;
        const float v0 = __ldcg(&sc[tid]);
        const float v1 = __ldcg(&sc[tid + 256]);

        s_sm[tid] = fmaxf(v0, v1);
        __syncthreads();
#pragma unroll
        for (int st = 128; st > 0; st >>= 1) {
            if (tid < st) s_sm[tid] = fmaxf(s_sm[tid], s_sm[tid + st]);
            __syncthreads();
        }
        const float mx = s_sm[0];
        __syncthreads();

        const float e0 = __expf(v0 - mx);
        const float e1 = __expf(v1 - mx);
        s_sm[tid] = e0 + e1;
        __syncthreads();
#pragma unroll
        for (int st = 128; st > 0; st >>= 1) {
            if (tid < st) s_sm[tid] += s_sm[tid + st];
            __syncthreads();
        }
        const float inv = 1.f / s_sm[0];

        out[b * S + tid]       = e0 * inv;
        out[b * S + tid + 256] = e1 * inv;

        // --- self-clean for the next launch ---
        if (tid == 0) {
            g_cnt[b] = 0;
            __threadfence();
            const int g = atomicAdd(&g_gcnt, 1);
            s_ticket = (g == B - 1) ? 1 : 0;
        }
        __syncthreads();
        if (s_ticket == 1) {
            // globally last block: all tickets issued => every block has read u2
            ((float4*)g_u2)[tid] = make_float4(0.f, 0.f, 0.f, 0.f);
            if (tid == 0) { g_gcnt = 0; g_ready = 0; }
        }
    }
}

// ---------------------------------------------------------------------------
// Inputs (metadata order): hidden[2,B,H], encoder_outputs[B,S,H],
//                          W[H,3H], b[H], v[H]
// hidden and b are mathematically irrelevant post-softmax (per-row constants).
// ---------------------------------------------------------------------------
extern "C" void kernel_launch(void* const* d_in, const int* in_sizes, int n_in,
                              void* d_out, int out_size) {
    const float* enc = (const float*)d_in[1];
    const float* W   = (const float*)d_in[2];
    const float* v   = (const float*)d_in[4];
    float* out = (float*)d_out;

    k_mega<<<NBLK, 256>>>(W, v, (const float4*)enc, out);
}

// round 5
// speedup vs baseline: 1.0063x; 1.0063x over previous
#include <cuda_runtime.h>
#include <cuda_bf16.h>

// Problem constants
#define H   1024
#define B   64
#define S   512
#define W3H 3072            // W row stride (3*H)
#define BLKS_PER_B 64       // fused kernel: blocks per batch row (8 rows each)

// Scratch (zero-initialized at module load; every launch self-cleans, so each
// graph replay is deterministic).
__device__ float g_u2[H];            // u2 = W[:, 2H:3H]^T v   (accumulated, then reset)
__device__ float g_scores[B * S];    // pre-softmax scores
__device__ int   g_cnt[B];           // per-b completion counters (reset by per-b last)
__device__ int   g_gcnt;             // global completion counter (reset by global last)

// ---------------------------------------------------------------------------
// Kernel 1: u2[k] += sum_h v[h] * W[h, 2H + k]       (g_u2 pre-zeroed)
// grid = (4, 32): x tiles k, y tiles h. atomicAdd partials (distinct addrs).
// ---------------------------------------------------------------------------
__global__ void k_u2(const float* __restrict__ W, const float* __restrict__ v) {
    const int tx = threadIdx.x & 63;   // k-float4 lane within block tile
    const int ty = threadIdx.x >> 6;   // h slice (0..3)
    const int k4 = blockIdx.x * 64 + tx;
    const int h0 = blockIdx.y * 32 + ty;

    float4 acc = make_float4(0.f, 0.f, 0.f, 0.f);
#pragma unroll
    for (int j = 0; j < 8; j++) {
        const int h = h0 + j * 4;
        const float vh = __ldg(&v[h]);
        const float4 w = __ldg((const float4*)(W + (size_t)h * W3H + 2 * H) + k4);
        acc.x += vh * w.x;
        acc.y += vh * w.y;
        acc.z += vh * w.z;
        acc.w += vh * w.w;
    }

    __shared__ float4 sm[4][64];
    sm[ty][tx] = acc;
    __syncthreads();
    if (ty == 0) {
        float4 s = sm[0][tx];
#pragma unroll
        for (int j = 1; j < 4; j++) {
            const float4 p = sm[j][tx];
            s.x += p.x; s.y += p.y; s.z += p.z; s.w += p.w;
        }
        float* dst = g_u2 + k4 * 4;
        atomicAdd(dst + 0, s.x);
        atomicAdd(dst + 1, s.y);
        atomicAdd(dst + 2, s.z);
        atomicAdd(dst + 3, s.w);
    }
}

// ---------------------------------------------------------------------------
// Kernel 2 (fused): scores + per-b softmax + self-clean.
// grid = 4096 blocks, 256 threads (8 warps -> 8 rows each).
// __launch_bounds__(256, 8): cap regs at 32 so 8 blocks/SM co-reside
// (R2's 22-reg standalone kernel at 8 blocks/SM hit 5.3 TB/s; the 37-reg
// fused versions at 6 blocks/SM only hit 4.3 - latency-bound scaling).
// ---------------------------------------------------------------------------
__global__ void __launch_bounds__(256, 8)
k_fused(const float4* __restrict__ enc, float* __restrict__ out) {
    const int b     = blockIdx.x >> 6;
    const int chunk = blockIdx.x & 63;
    const int warp  = threadIdx.x >> 5;
    const int lane  = threadIdx.x & 31;
    const int row   = b * S + chunk * 8 + warp;   // global row in [0, B*S)

    const float4* __restrict__ rp = enc + (size_t)row * (H / 4);
    const float4* __restrict__ u  = (const float4*)g_u2;

    float acc = 0.f;
#pragma unroll
    for (int j = 0; j < 8; j++) {
        const float4 e = __ldg(&rp[lane + j * 32]);
        const float4 w = __ldg(&u[lane + j * 32]);   // L1-hot after first touch
        acc += e.x * w.x + e.y * w.y + e.z * w.z + e.w * w.w;
    }
#pragma unroll
    for (int off = 16; off > 0; off >>= 1)
        acc += __shfl_xor_sync(0xffffffffu, acc, off);
    if (lane == 0) g_scores[row] = acc;

    // --- last-block-per-b does the softmax ---
    __shared__ int s_ticket;
    __threadfence();                     // make score writes visible chip-wide
    __syncthreads();                     // all warps of this block done
    if (threadIdx.x == 0)
        s_ticket = atomicAdd(&g_cnt[b], 1);
    __syncthreads();

    if (s_ticket == BLKS_PER_B - 1) {
        const int tid = threadIdx.x;     // 256
        const float* sc = g_scores + b * S;
        const float v0 = __ldcg(&sc[tid]);
        const float v1 = __ldcg(&sc[tid + 256]);

        __shared__ float sm[256];
        sm[tid] = fmaxf(v0, v1);
        __syncthreads();
#pragma unroll
        for (int st = 128; st > 0; st >>= 1) {
            if (tid < st) sm[tid] = fmaxf(sm[tid], sm[tid + st]);
            __syncthreads();
        }
        const float mx = sm[0];
        __syncthreads();

        const float e0 = __expf(v0 - mx);
        const float e1 = __expf(v1 - mx);
        sm[tid] = e0 + e1;
        __syncthreads();
#pragma unroll
        for (int st = 128; st > 0; st >>= 1) {
            if (tid < st) sm[tid] += sm[tid + st];
            __syncthreads();
        }
        const float inv = 1.f / sm[0];

        out[b * S + tid]       = e0 * inv;
        out[b * S + tid + 256] = e1 * inv;

        // --- self-clean for the next launch ---
        if (tid == 0) {
            g_cnt[b] = 0;
            __threadfence();
            const int g = atomicAdd(&g_gcnt, 1);
            s_ticket = (g == B - 1) ? 1 : 0;
        }
        __syncthreads();
        if (s_ticket == 1) {
            // globally last block: all per-b softmaxes done => u2 fully consumed
            ((float4*)g_u2)[tid] = make_float4(0.f, 0.f, 0.f, 0.f);
            if (tid == 0) g_gcnt = 0;
        }
    }
}

// ---------------------------------------------------------------------------
// Inputs (metadata order): hidden[2,B,H], encoder_outputs[B,S,H],
//                          W[H,3H], b[H], v[H]
// hidden and b are mathematically irrelevant post-softmax (per-row constants).
// ---------------------------------------------------------------------------
extern "C" void kernel_launch(void* const* d_in, const int* in_sizes, int n_in,
                              void* d_out, int out_size) {
    const float* enc = (const float*)d_in[1];
    const float* W   = (const float*)d_in[2];
    const float* v   = (const float*)d_in[4];
    float* out = (float*)d_out;

    {
        dim3 grid(4, 32);
        k_u2<<<grid, 256>>>(W, v);
    }
    k_fused<<<B * BLKS_PER_B, 256>>>((const float4*)enc, out);
}

// round 6
// speedup vs baseline: 1.0073x; 1.0009x over previous
#include <cuda_runtime.h>
#include <cuda_bf16.h>

// Problem constants
#define H   1024
#define B   64
#define S   512
#define W3H 3072            // W row stride (3*H)
#define BLKS_PER_B 64       // fused kernel: blocks per batch row (8 rows each)

// Scratch (zero-initialized at module load; every launch self-cleans, so each
// graph replay is deterministic).
__device__ float g_u2[H];            // u2 = W[:, 2H:3H]^T v   (accumulated, then reset)
__device__ float g_scores[B * S];    // pre-softmax scores
__device__ int   g_cnt[B];           // per-b completion counters (reset by per-b last)
__device__ int   g_gcnt;             // global completion counter (reset by global last)

// ---------------------------------------------------------------------------
// Kernel 1: u2[k] += sum_h v[h] * W[h, 2H + k]       (g_u2 pre-zeroed)
// grid = (4, 32): x tiles k, y tiles h. atomicAdd partials (distinct addrs).
// ---------------------------------------------------------------------------
__global__ void k_u2(const float* __restrict__ W, const float* __restrict__ v) {
    const int tx = threadIdx.x & 63;   // k-float4 lane within block tile
    const int ty = threadIdx.x >> 6;   // h slice (0..3)
    const int k4 = blockIdx.x * 64 + tx;
    const int h0 = blockIdx.y * 32 + ty;

    float4 acc = make_float4(0.f, 0.f, 0.f, 0.f);
#pragma unroll
    for (int j = 0; j < 8; j++) {
        const int h = h0 + j * 4;
        const float vh = __ldg(&v[h]);
        const float4 w = __ldg((const float4*)(W + (size_t)h * W3H + 2 * H) + k4);
        acc.x += vh * w.x;
        acc.y += vh * w.y;
        acc.z += vh * w.z;
        acc.w += vh * w.w;
    }

    __shared__ float4 sm[4][64];
    sm[ty][tx] = acc;
    __syncthreads();
    if (ty == 0) {
        float4 s = sm[0][tx];
#pragma unroll
        for (int j = 1; j < 4; j++) {
            const float4 p = sm[j][tx];
            s.x += p.x; s.y += p.y; s.z += p.z; s.w += p.w;
        }
        float* dst = g_u2 + k4 * 4;
        atomicAdd(dst + 0, s.x);
        atomicAdd(dst + 1, s.y);
        atomicAdd(dst + 2, s.z);
        atomicAdd(dst + 3, s.w);
    }
}

// ---------------------------------------------------------------------------
// Kernel 2 (fused): scores + per-b softmax + self-clean.
// grid = 4096 blocks, 256 threads (8 warps -> 8 rows each).
// Epilogue protocol is SINGLE-THREAD release/acquire:
//   all warps store scores -> __syncthreads() (CTA-visible) ->
//   tid0: fence.gpu (cumulative release) + atomicAdd ticket.
// Consumer (ticket==63): tid0 fence.gpu (acquire) -> __syncthreads() -> reads.
// This removes the per-thread MEMBAR.GPU storm that cost ~6-10us in R3-R5.
// ---------------------------------------------------------------------------
__global__ void __launch_bounds__(256, 8)
k_fused(const float4* __restrict__ enc, float* __restrict__ out) {
    const int b     = blockIdx.x >> 6;
    const int chunk = blockIdx.x & 63;
    const int warp  = threadIdx.x >> 5;
    const int lane  = threadIdx.x & 31;
    const int tid   = threadIdx.x;
    const int row   = b * S + chunk * 8 + warp;   // global row in [0, B*S)

    const float4* __restrict__ rp = enc + (size_t)row * (H / 4);
    const float4* __restrict__ u  = (const float4*)g_u2;

    float acc = 0.f;
#pragma unroll
    for (int j = 0; j < 8; j++) {
        const float4 e = __ldg(&rp[lane + j * 32]);
        const float4 w = __ldg(&u[lane + j * 32]);   // L1-hot after first touch
        acc += e.x * w.x + e.y * w.y + e.z * w.z + e.w * w.w;
    }
#pragma unroll
    for (int off = 16; off > 0; off >>= 1)
        acc += __shfl_xor_sync(0xffffffffu, acc, off);
    if (lane == 0) g_scores[row] = acc;

    // --- single-thread release + ticket ---
    __shared__ int s_ticket;
    __syncthreads();                     // block's score STGs CTA-visible
    if (tid == 0) {
        __threadfence();                 // cumulative release to gpu scope
        s_ticket = atomicAdd(&g_cnt[b], 1);
        if (s_ticket == BLKS_PER_B - 1)
            __threadfence();             // acquire for the re-reads below
    }
    __syncthreads();

    if (s_ticket == BLKS_PER_B - 1) {
        const float* sc = g_scores + b * S;
        const float v0 = __ldcg(&sc[tid]);
        const float v1 = __ldcg(&sc[tid + 256]);

        __shared__ float sm[256];
        sm[tid] = fmaxf(v0, v1);
        __syncthreads();
#pragma unroll
        for (int st = 128; st > 0; st >>= 1) {
            if (tid < st) sm[tid] = fmaxf(sm[tid], sm[tid + st]);
            __syncthreads();
        }
        const float mx = sm[0];
        __syncthreads();

        const float e0 = __expf(v0 - mx);
        const float e1 = __expf(v1 - mx);
        sm[tid] = e0 + e1;
        __syncthreads();
#pragma unroll
        for (int st = 128; st > 0; st >>= 1) {
            if (tid < st) sm[tid] += sm[tid + st];
            __syncthreads();
        }
        const float inv = 1.f / sm[0];

        out[b * S + tid]       = e0 * inv;
        out[b * S + tid + 256] = e1 * inv;

        // --- self-clean for the next launch ---
        if (tid == 0) {
            g_cnt[b] = 0;
            __threadfence();
            const int g = atomicAdd(&g_gcnt, 1);
            s_ticket = (g == B - 1) ? 1 : 0;
        }
        __syncthreads();
        if (s_ticket == 1) {
            // globally last block: all per-b softmaxes done => u2 fully consumed
            ((float4*)g_u2)[tid] = make_float4(0.f, 0.f, 0.f, 0.f);
            if (tid == 0) g_gcnt = 0;
        }
    }
}

// ---------------------------------------------------------------------------
// Inputs (metadata order): hidden[2,B,H], encoder_outputs[B,S,H],
//                          W[H,3H], b[H], v[H]
// hidden and b are mathematically irrelevant post-softmax (per-row constants).
// ---------------------------------------------------------------------------
extern "C" void kernel_launch(void* const* d_in, const int* in_sizes, int n_in,
                              void* d_out, int out_size) {
    const float* enc = (const float*)d_in[1];
    const float* W   = (const float*)d_in[2];
    const float* v   = (const float*)d_in[4];
    float* out = (float*)d_out;

    {
        dim3 grid(4, 32);
        k_u2<<<grid, 256>>>(W, v);
    }
    k_fused<<<B * BLKS_PER_B, 256>>>((const float4*)enc, out);
}